// round 8
// baseline (speedup 1.0000x reference)
#include <cuda_runtime.h>
#include <cuda_bf16.h>
#include <math.h>
#include <stdint.h>

#define NN 4096          // D*W*H = 16*16*16
#define LL 21            // labels
#define LN (LL * NN)
#define NCTA 148
#define NT 512

// ---------------- device scratch ----------------
__device__ __nv_bfloat16 g_Kb[16777216];   // 4096x4096 bilateral kernel bf16 (32 MB)
__device__ float         g_F[NN * 8];      // features f0..f5, h, pad
__device__ float         g_q[LN];          // softmax (fp32, spatial path)
__device__ __nv_bfloat16 g_qb[24 * NN];    // bf16 q rows 0..20, row21=ones, 22..23=0
__device__ float         g_A[LN];          // spatial filter result
__device__ float         g_P[NN * 32];     // bilateral GEMM out, col 21 = normalizer
__device__ float         g_cur[LN];        // logits between iterations
__device__ float         g_Msp[LL * LL];
__device__ float         g_Mbi[LL * LL];
__device__ float         g_G[16];
__device__ float         g_S[16];

// ---------------- grid barrier (148 co-resident CTAs) ----------------
__device__ unsigned g_bcnt = 0;
__device__ volatile unsigned g_bgen = 0;

__device__ __forceinline__ void gsync() {
    __syncthreads();
    if (threadIdx.x == 0) {
        unsigned gen = g_bgen;
        __threadfence();
        if (atomicAdd(&g_bcnt, 1u) == NCTA - 1) {
            atomicExch(&g_bcnt, 0u);
            __threadfence();
            g_bgen = gen + 1;
        } else {
            while (g_bgen == gen) { __nanosleep(64); }
            __threadfence();
        }
    }
    __syncthreads();
}

// ---------------- HMMA helper (legal on plain sm_103 PTX) ----------------
__device__ __forceinline__ void mma16816(float* c, const uint32_t* a, const uint32_t* b) {
    asm volatile(
        "mma.sync.aligned.m16n8k16.row.col.f32.bf16.bf16.f32 "
        "{%0,%1,%2,%3}, {%4,%5,%6,%7}, {%8,%9}, {%0,%1,%2,%3};"
        : "+f"(c[0]), "+f"(c[1]), "+f"(c[2]), "+f"(c[3])
        : "r"(a[0]), "r"(a[1]), "r"(a[2]), "r"(a[3]), "r"(b[0]), "r"(b[1]));
}

// ---------------- the single persistent kernel ----------------
__global__ void __launch_bounds__(NT) mega_k(const float* __restrict__ img,
                                             const float* __restrict__ logits,
                                             const float* __restrict__ wsp,
                                             const float* __restrict__ wbi,
                                             const float* __restrict__ comp,
                                             float* __restrict__ out) {
    const int tid = threadIdx.x;
    const int bid = blockIdx.x;
    const int wid = tid >> 5;
    const int lane = tid & 31;
    const int gid = bid * NT + tid;

    __shared__ float s0[4096];
    __shared__ float s1[4096];
    __shared__ float Gs[16];

    // ===== P0: setup tables / small mats / features =====
    if (bid == 0) {
        if (tid < 16) {
            g_G[tid] = expf(-0.5f * (float)(tid * tid));
            float s = 0.f;
            for (int u = 0; u < 16; u++) {
                int d = tid - u;
                s += expf(-0.5f * (float)(d * d));
            }
            g_S[tid] = s;
        }
        if (tid < LL * LL) {
            int l = tid / LL, m = tid % LL;
            float s1v = 0.f, s2v = 0.f;
            for (int k = 0; k < LL; k++) {
                float c = comp[l * LL + k];
                s1v += c * wsp[k * LL + m];
                s2v += c * wbi[k * LL + m];
            }
            g_Msp[tid] = s1v;
            g_Mbi[tid] = s2v;
        }
    }
    if (gid < NN) {
        int n = gid;
        float z = (float)(n >> 8);
        float y = (float)((n >> 4) & 15);
        float x = (float)(n & 15);
        const float ia = 1.f / 67.f, ib = 1.f / 3.f;
        float f0 = z * ia, f1 = y * ia, f2 = x * ia;
        float f3 = img[n] * ib;
        float f4 = img[NN + n] * ib;
        float f5 = img[2 * NN + n] * ib;
        float h = -0.5f * (f0 * f0 + f1 * f1 + f2 * f2 + f3 * f3 + f4 * f4 + f5 * f5);
        float* p = g_F + (size_t)n * 8;
        p[0] = f0; p[1] = f1; p[2] = f2; p[3] = f3; p[4] = f4; p[5] = f5; p[6] = h; p[7] = 0.f;
        g_qb[21 * NN + n] = __float2bfloat16(1.0f);
        g_qb[22 * NN + n] = __float2bfloat16(0.0f);
        g_qb[23 * NN + n] = __float2bfloat16(0.0f);
    }
    gsync();

    // ===== P1: build bilateral kernel K (bf16) =====
    // unit = (jt 0..31, it 0..63): 128 j-cols (lane*4) x 64 i-rows. 2048 units, 2368 warps.
    {
        int wg = bid * (NT / 32) + wid;
        if (wg < 2048) {
            int jt = wg & 31, it0 = wg >> 5;
            int jb = jt * 128 + lane * 4;
            float fj[4][7];
#pragma unroll
            for (int s = 0; s < 4; s++) {
                const float4* fp = (const float4*)(g_F + (size_t)(jb + s) * 8);
                float4 a = fp[0];
                float4 b = fp[1];
                fj[s][0] = a.x; fj[s][1] = a.y; fj[s][2] = a.z; fj[s][3] = a.w;
                fj[s][4] = b.x; fj[s][5] = b.y; fj[s][6] = b.z;
            }
            int ibase = it0 * 64;
            for (int ii = 0; ii < 64; ii++) {
                int i = ibase + ii;
                const float4* fp = (const float4*)(g_F + (size_t)i * 8);
                float4 a = fp[0];
                float4 b = fp[1];  // b.z = h_i
                float o[4];
#pragma unroll
                for (int s = 0; s < 4; s++) {
                    float e = b.z + fj[s][6]
                            + a.x * fj[s][0] + a.y * fj[s][1] + a.z * fj[s][2]
                            + b.x * fj[s][4] + b.y * fj[s][5] + a.w * fj[s][3];
                    o[s] = __expf(fminf(e, 0.f));
                }
                __nv_bfloat162 p0 = __floats2bfloat162_rn(o[0], o[1]);
                __nv_bfloat162 p1 = __floats2bfloat162_rn(o[2], o[3]);
                uint2 v;
                v.x = *(uint32_t*)&p0;
                v.y = *(uint32_t*)&p1;
                *(uint2*)(g_Kb + (size_t)i * NN + jb) = v;
            }
        }
    }
    gsync();

    // ===== mean-field iterations =====
    for (int it = 0; it < 5; it++) {
        // ---- softmax + qb emit + zero P (voxel per thread) ----
        if (gid < NN) {
            int n = gid;
            const float* src = (it == 0) ? logits : g_cur;
            float v[LL];
            float m = -1e30f;
#pragma unroll
            for (int l = 0; l < LL; l++) {
                v[l] = src[l * NN + n];
                m = fmaxf(m, v[l]);
            }
            float s = 0.f;
#pragma unroll
            for (int l = 0; l < LL; l++) {
                v[l] = __expf(v[l] - m);
                s += v[l];
            }
            float inv = 1.f / s;
#pragma unroll
            for (int l = 0; l < LL; l++) {
                float q = v[l] * inv;
                g_q[l * NN + n] = q;
                g_qb[l * NN + n] = __float2bfloat16(q);
            }
            float4 z4 = make_float4(0.f, 0.f, 0.f, 0.f);
            float4* P4 = (float4*)(g_P + (size_t)n * 32);
#pragma unroll
            for (int k = 0; k < 8; k++) P4[k] = z4;
        }
        gsync();

        // ---- spatial (CTAs 0..20) in parallel with bilateral GEMM (CTAs 21..147) ----
        if (bid < LL) {
            // separable 16-tap Gaussian, label = bid
            int l = bid;
            if (tid < 16) Gs[tid] = g_G[tid];
            const float* src = g_q + (size_t)l * NN;
#pragma unroll
            for (int k = 0; k < 8; k++) s0[tid + k * NT] = src[tid + k * NT];
            __syncthreads();
#pragma unroll
            for (int k = 0; k < 8; k++) {
                int n = tid + k * NT;
                int x = n & 15, b = n - x;
                float a = 0.f;
#pragma unroll
                for (int tt = 0; tt < 16; tt++) {
                    int d = x - tt; d = d < 0 ? -d : d;
                    a += Gs[d] * s0[b + tt];
                }
                s1[n] = a;
            }
            __syncthreads();
#pragma unroll
            for (int k = 0; k < 8; k++) {
                int n = tid + k * NT;
                int y = (n >> 4) & 15, b = n - (y << 4);
                float a = 0.f;
#pragma unroll
                for (int tt = 0; tt < 16; tt++) {
                    int d = y - tt; d = d < 0 ? -d : d;
                    a += Gs[d] * s1[b + (tt << 4)];
                }
                s0[n] = a;
            }
            __syncthreads();
            float* dst = g_A + (size_t)l * NN;
#pragma unroll
            for (int k = 0; k < 8; k++) {
                int n = tid + k * NT;
                int z = n >> 8, b = n & 255;
                float a = 0.f;
#pragma unroll
                for (int tt = 0; tt < 16; tt++) {
                    int d = z - tt; d = d < 0 ? -d : d;
                    a += Gs[d] * s0[b + (tt << 8)];
                }
                dst[n] = a;
            }
        } else {
            // HMMA gemm: units = (row-tile 0..127 of 32 rows, ksplit 0..15 of k=256)
            int wg2 = (bid - LL) * (NT / 32) + wid;
            int g = lane >> 2, t = lane & 3;
            const __nv_bfloat16* pb[3];
            pb[0] = g_qb + (size_t)(g)*NN;
            pb[1] = g_qb + (size_t)(8 + g) * NN;
            pb[2] = g_qb + (size_t)(16 + g) * NN;
            for (int u = wg2; u < 2048; u += 127 * (NT / 32)) {
                int jt = u >> 4;
                int ks = u & 15;
                int rb = jt * 32;
                int k0 = ks * 256;
                const __nv_bfloat16* pa[4];
                pa[0] = g_Kb + (size_t)(rb + g) * NN;
                pa[1] = g_Kb + (size_t)(rb + g + 8) * NN;
                pa[2] = g_Kb + (size_t)(rb + 16 + g) * NN;
                pa[3] = g_Kb + (size_t)(rb + 16 + g + 8) * NN;

                float acc[2][3][4];
#pragma unroll
                for (int m = 0; m < 2; m++)
#pragma unroll
                    for (int n = 0; n < 3; n++)
#pragma unroll
                        for (int r = 0; r < 4; r++) acc[m][n][r] = 0.f;

#pragma unroll 2
                for (int kss = 0; kss < 16; kss++) {
                    int kk = k0 + kss * 16 + t * 2;
                    uint32_t a0[4], a1[4], b[3][2];
                    a0[0] = *(const uint32_t*)(pa[0] + kk);
                    a0[1] = *(const uint32_t*)(pa[1] + kk);
                    a0[2] = *(const uint32_t*)(pa[0] + kk + 8);
                    a0[3] = *(const uint32_t*)(pa[1] + kk + 8);
                    a1[0] = *(const uint32_t*)(pa[2] + kk);
                    a1[1] = *(const uint32_t*)(pa[3] + kk);
                    a1[2] = *(const uint32_t*)(pa[2] + kk + 8);
                    a1[3] = *(const uint32_t*)(pa[3] + kk + 8);
#pragma unroll
                    for (int n = 0; n < 3; n++) {
                        b[n][0] = *(const uint32_t*)(pb[n] + kk);
                        b[n][1] = *(const uint32_t*)(pb[n] + kk + 8);
                    }
#pragma unroll
                    for (int n = 0; n < 3; n++) {
                        mma16816(acc[0][n], a0, b[n]);
                        mma16816(acc[1][n], a1, b[n]);
                    }
                }
#pragma unroll
                for (int m = 0; m < 2; m++) {
                    int r0 = rb + m * 16 + g;
#pragma unroll
                    for (int n = 0; n < 3; n++) {
                        int c = n * 8 + t * 2;
                        if (c < 21) {
                            atomicAdd(g_P + (size_t)r0 * 32 + c, acc[m][n][0]);
                            atomicAdd(g_P + (size_t)r0 * 32 + c + 1, acc[m][n][1]);
                            atomicAdd(g_P + (size_t)(r0 + 8) * 32 + c, acc[m][n][2]);
                            atomicAdd(g_P + (size_t)(r0 + 8) * 32 + c + 1, acc[m][n][3]);
                        }
                    }
                }
            }
        }
        gsync();

        // ---- combine: (l,n)-parallel across all threads ----
        for (int idx = gid; idx < LN; idx += NCTA * NT) {
            int l = idx >> 12;
            int n = idx & (NN - 1);
            int z = n >> 8, y = (n >> 4) & 15, x = n & 15;
            float invs = 1.f / (g_S[z] * g_S[y] * g_S[x]);
            const float* Pn = g_P + (size_t)n * 32;
            float invb = 1.f / Pn[21];
            const float* msp = g_Msp + l * LL;
            const float* mbi = g_Mbi + l * LL;
            float ssp = 0.f, sbi = 0.f;
#pragma unroll
            for (int m = 0; m < LL; m++) {
                ssp += msp[m] * g_A[m * NN + n];
                sbi += mbi[m] * Pn[m];
            }
            float val = logits[idx] + ssp * invs + sbi * invb;
            if (it == 4) out[idx] = val;
            else g_cur[idx] = val;
        }
        if (it < 4) gsync();
    }
}

// ---------------- host launch: ONE kernel, one graph node ----------------
extern "C" void kernel_launch(void* const* d_in, const int* in_sizes, int n_in,
                              void* d_out, int out_size) {
    (void)in_sizes; (void)n_in; (void)out_size;
    const float* image  = (const float*)d_in[0];
    const float* logits = (const float*)d_in[1];
    const float* wsp    = (const float*)d_in[2];
    const float* wbi    = (const float*)d_in[3];
    const float* comp   = (const float*)d_in[4];
    float* out = (float*)d_out;

    mega_k<<<NCTA, NT>>>(image, logits, wsp, wbi, comp, out);
}

// round 11
// speedup vs baseline: 1.7890x; 1.7890x over previous
#include <cuda_runtime.h>
#include <cuda_bf16.h>
#include <math.h>
#include <stdint.h>

#define NN 4096          // D*W*H = 16*16*16
#define LL 21            // labels
#define LN (LL * NN)

// ---------------- device scratch ----------------
__device__ __nv_bfloat16 g_Kb[16777216];   // 4096x4096 bilateral kernel bf16 (32 MB, L2-resident)
__device__ float         g_F[NN * 8];      // features f0..f5, h, pad
__device__ float         g_q[LN];          // softmax out (fp32, spatial path)
__device__ __nv_bfloat16 g_qb[24 * NN];    // bf16 q rows 0..20, row21=ones, 22..23=0
__device__ float         g_A[LN];          // spatial filter result
__device__ float         g_P[NN * 32];     // bilateral GEMM out, col 21 = normalizer
__device__ float         g_Msp[LL * LL];
__device__ float         g_Mbi[LL * LL];
__device__ float         g_G[16];
__device__ float         g_S[16];

// ---------------- HMMA helper (plain sm_103 PTX legal) ----------------
__device__ __forceinline__ void mma16816(float* c, const uint32_t* a, const uint32_t* b) {
    asm volatile(
        "mma.sync.aligned.m16n8k16.row.col.f32.bf16.bf16.f32 "
        "{%0,%1,%2,%3}, {%4,%5,%6,%7}, {%8,%9}, {%0,%1,%2,%3};"
        : "+f"(c[0]), "+f"(c[1]), "+f"(c[2]), "+f"(c[3])
        : "r"(a[0]), "r"(a[1]), "r"(a[2]), "r"(a[3]), "r"(b[0]), "r"(b[1]));
}

// ---------------- setup ----------------
__global__ void setup_k(const float* __restrict__ wsp,
                        const float* __restrict__ wbi,
                        const float* __restrict__ comp) {
    int t = threadIdx.x;
    if (t < 16) {
        g_G[t] = expf(-0.5f * (float)(t * t));
        float s = 0.f;
        for (int u = 0; u < 16; u++) {
            int d = t - u;
            s += expf(-0.5f * (float)(d * d));
        }
        g_S[t] = s;
    }
    if (t < LL * LL) {
        int l = t / LL, m = t % LL;
        float s1 = 0.f, s2 = 0.f;
        for (int k = 0; k < LL; k++) {
            float c = comp[l * LL + k];
            s1 += c * wsp[k * LL + m];
            s2 += c * wbi[k * LL + m];
        }
        g_Msp[t] = s1;
        g_Mbi[t] = s2;
    }
}

__global__ void featq_k(const float* __restrict__ img) {
    int n = blockIdx.x * 256 + threadIdx.x;
    if (n >= NN) return;
    float z = (float)(n >> 8);
    float y = (float)((n >> 4) & 15);
    float x = (float)(n & 15);
    const float ia = 1.f / 67.f, ib = 1.f / 3.f;
    float f0 = z * ia, f1 = y * ia, f2 = x * ia;
    float f3 = img[n] * ib;
    float f4 = img[NN + n] * ib;
    float f5 = img[2 * NN + n] * ib;
    float h = -0.5f * (f0 * f0 + f1 * f1 + f2 * f2 + f3 * f3 + f4 * f4 + f5 * f5);
    float* p = g_F + (size_t)n * 8;
    p[0] = f0; p[1] = f1; p[2] = f2; p[3] = f3; p[4] = f4; p[5] = f5; p[6] = h; p[7] = 0.f;
    g_qb[21 * NN + n] = __float2bfloat16(1.0f);
    g_qb[22 * NN + n] = __float2bfloat16(0.0f);
    g_qb[23 * NN + n] = __float2bfloat16(0.0f);
}

// ---------------- K build: grid (32 jt, 128 ib), 128 thr; warp does 8 i-rows x 128 j ----------------
__global__ void __launch_bounds__(128) buildK_k() {
    int w = threadIdx.x >> 5;
    int lane = threadIdx.x & 31;
    int jb = blockIdx.x * 128 + lane * 4;
    int ibase = blockIdx.y * 32 + w * 8;

    float fj[4][7];
#pragma unroll
    for (int s = 0; s < 4; s++) {
        const float4* fp = (const float4*)(g_F + (size_t)(jb + s) * 8);
        float4 a = fp[0];
        float4 b = fp[1];
        fj[s][0] = a.x; fj[s][1] = a.y; fj[s][2] = a.z; fj[s][3] = a.w;
        fj[s][4] = b.x; fj[s][5] = b.y; fj[s][6] = b.z;
    }

#pragma unroll 2
    for (int ii = 0; ii < 8; ii++) {
        int i = ibase + ii;
        const float4* fp = (const float4*)(g_F + (size_t)i * 8);
        float4 a = fp[0];
        float4 b = fp[1];  // b.z = h_i
        float o[4];
#pragma unroll
        for (int s = 0; s < 4; s++) {
            float e = b.z + fj[s][6]
                    + a.x * fj[s][0] + a.y * fj[s][1] + a.z * fj[s][2]
                    + b.x * fj[s][4] + b.y * fj[s][5] + a.w * fj[s][3];
            o[s] = __expf(fminf(e, 0.f));
        }
        __nv_bfloat162 p0 = __floats2bfloat162_rn(o[0], o[1]);
        __nv_bfloat162 p1 = __floats2bfloat162_rn(o[2], o[3]);
        uint2 v;
        v.x = *(uint32_t*)&p0;
        v.y = *(uint32_t*)&p1;
        *(uint2*)(g_Kb + (size_t)i * NN + jb) = v;
    }
}

// ---------------- initial softmax (from logits) + qb + zero P ----------------
__global__ void softmax0_k(const float* __restrict__ logits) {
    int n = blockIdx.x * 64 + threadIdx.x;
    float v[LL];
    float m = -1e30f;
#pragma unroll
    for (int l = 0; l < LL; l++) {
        v[l] = logits[l * NN + n];
        m = fmaxf(m, v[l]);
    }
    float s = 0.f;
#pragma unroll
    for (int l = 0; l < LL; l++) {
        v[l] = __expf(v[l] - m);
        s += v[l];
    }
    float inv = 1.f / s;
#pragma unroll
    for (int l = 0; l < LL; l++) {
        float q = v[l] * inv;
        g_q[l * NN + n] = q;
        g_qb[l * NN + n] = __float2bfloat16(q);
    }
    float4 z4 = make_float4(0.f, 0.f, 0.f, 0.f);
    float4* P4 = (float4*)(g_P + (size_t)n * 32);
#pragma unroll
    for (int k = 0; k < 8; k++) P4[k] = z4;
}

// ---------------- fused spatial + bilateral gemm. grid 149 x 256 thr ----------------
// blocks 0..127: gemm (8 warps each -> 1024 warp-units: 128 row-tiles x 8 k-splits)
// blocks 128..148: separable spatial filter, label = bid-128
__global__ void __launch_bounds__(256) sg_k() {
    __shared__ float s0[4096];
    __shared__ float s1[4096];
    __shared__ float Gs[16];
    const int tid = threadIdx.x;
    const int bid = blockIdx.x;

    if (bid >= 128) {
        int l = bid - 128;
        if (tid < 16) Gs[tid] = g_G[tid];
        const float* src = g_q + (size_t)l * NN;
#pragma unroll
        for (int k = 0; k < 16; k++) s0[tid + k * 256] = src[tid + k * 256];
        __syncthreads();
#pragma unroll
        for (int k = 0; k < 16; k++) {
            int n = tid + k * 256;
            int x = n & 15, b = n - x;
            float a = 0.f;
#pragma unroll
            for (int tt = 0; tt < 16; tt++) {
                int d = x - tt; d = d < 0 ? -d : d;
                a += Gs[d] * s0[b + tt];
            }
            s1[n] = a;
        }
        __syncthreads();
#pragma unroll
        for (int k = 0; k < 16; k++) {
            int n = tid + k * 256;
            int y = (n >> 4) & 15, b = n - (y << 4);
            float a = 0.f;
#pragma unroll
            for (int tt = 0; tt < 16; tt++) {
                int d = y - tt; d = d < 0 ? -d : d;
                a += Gs[d] * s1[b + (tt << 4)];
            }
            s0[n] = a;
        }
        __syncthreads();
        float* dst = g_A + (size_t)(bid - 128) * NN;
#pragma unroll
        for (int k = 0; k < 16; k++) {
            int n = tid + k * 256;
            int z = n >> 8, b = n & 255;
            float a = 0.f;
#pragma unroll
            for (int tt = 0; tt < 16; tt++) {
                int d = z - tt; d = d < 0 ? -d : d;
                a += Gs[d] * s0[b + (tt << 8)];
            }
            dst[n] = a;
        }
        return;
    }

    // ---- gemm path ----
    int wid = tid >> 5, lane = tid & 31;
    int u = bid * 8 + wid;            // 0..1023
    int jt = u >> 3, ks = u & 7;
    int rb = jt * 32;
    int k0 = ks * 512;
    int g = lane >> 2, t = lane & 3;

    const __nv_bfloat16* pa[4];
    pa[0] = g_Kb + (size_t)(rb + g) * NN;
    pa[1] = g_Kb + (size_t)(rb + g + 8) * NN;
    pa[2] = g_Kb + (size_t)(rb + 16 + g) * NN;
    pa[3] = g_Kb + (size_t)(rb + 16 + g + 8) * NN;
    const __nv_bfloat16* pb[3];
    pb[0] = g_qb + (size_t)(g)*NN;
    pb[1] = g_qb + (size_t)(8 + g) * NN;
    pb[2] = g_qb + (size_t)(16 + g) * NN;

    float acc[2][3][4];
#pragma unroll
    for (int m = 0; m < 2; m++)
#pragma unroll
        for (int n = 0; n < 3; n++)
#pragma unroll
            for (int r = 0; r < 4; r++) acc[m][n][r] = 0.f;

#pragma unroll 2
    for (int kss = 0; kss < 32; kss++) {
        int kk = k0 + kss * 16 + t * 2;
        uint32_t a0[4], a1[4], b[3][2];
        a0[0] = *(const uint32_t*)(pa[0] + kk);
        a0[1] = *(const uint32_t*)(pa[1] + kk);
        a0[2] = *(const uint32_t*)(pa[0] + kk + 8);
        a0[3] = *(const uint32_t*)(pa[1] + kk + 8);
        a1[0] = *(const uint32_t*)(pa[2] + kk);
        a1[1] = *(const uint32_t*)(pa[3] + kk);
        a1[2] = *(const uint32_t*)(pa[2] + kk + 8);
        a1[3] = *(const uint32_t*)(pa[3] + kk + 8);
#pragma unroll
        for (int n = 0; n < 3; n++) {
            b[n][0] = *(const uint32_t*)(pb[n] + kk);
            b[n][1] = *(const uint32_t*)(pb[n] + kk + 8);
        }
#pragma unroll
        for (int n = 0; n < 3; n++) {
            mma16816(acc[0][n], a0, b[n]);
            mma16816(acc[1][n], a1, b[n]);
        }
    }

#pragma unroll
    for (int m = 0; m < 2; m++) {
        int r0 = rb + m * 16 + g;
#pragma unroll
        for (int n = 0; n < 3; n++) {
            int c = n * 8 + t * 2;
            if (c < 21) {
                atomicAdd(g_P + (size_t)r0 * 32 + c, acc[m][n][0]);
                atomicAdd(g_P + (size_t)r0 * 32 + c + 1, acc[m][n][1]);
                atomicAdd(g_P + (size_t)(r0 + 8) * 32 + c, acc[m][n][2]);
                atomicAdd(g_P + (size_t)(r0 + 8) * 32 + c + 1, acc[m][n][3]);
            }
        }
    }
}

// ---------------- fused combine + softmax (+ qb + zero P); last iter writes out ----------------
__global__ void __launch_bounds__(64) cs_k(const float* __restrict__ logits,
                                           float* __restrict__ out, int last) {
    __shared__ float Ms[LL * LL];
    __shared__ float Mb[LL * LL];
    int tid = threadIdx.x;
    for (int i = tid; i < LL * LL; i += 64) {
        Ms[i] = g_Msp[i];
        Mb[i] = g_Mbi[i];
    }
    __syncthreads();

    int n = blockIdx.x * 64 + tid;
    int z = n >> 8, y = (n >> 4) & 15, x = n & 15;
    float invs = 1.f / (g_S[z] * g_S[y] * g_S[x]);

    float p[22];
    {
        const float4* P4 = (const float4*)(g_P + (size_t)n * 32);
#pragma unroll
        for (int k = 0; k < 5; k++) {
            float4 v = P4[k];
            p[k * 4] = v.x; p[k * 4 + 1] = v.y; p[k * 4 + 2] = v.z; p[k * 4 + 3] = v.w;
        }
        float4 v = P4[5];
        p[20] = v.x; p[21] = v.y;
    }
    float invb = 1.f / p[21];

    float a[LL];
#pragma unroll
    for (int m = 0; m < LL; m++) a[m] = g_A[m * NN + n];

    float val[LL];
    float mx = -1e30f;
#pragma unroll
    for (int l = 0; l < LL; l++) {
        const float* ms = Ms + l * LL;
        const float* mb = Mb + l * LL;
        float ssp = 0.f, sbi = 0.f;
#pragma unroll
        for (int m = 0; m < LL; m++) {
            ssp += ms[m] * a[m];
            sbi += mb[m] * p[m];
        }
        float v = logits[l * NN + n] + ssp * invs + sbi * invb;
        val[l] = v;
        mx = fmaxf(mx, v);
    }

    if (last) {
#pragma unroll
        for (int l = 0; l < LL; l++) out[l * NN + n] = val[l];
        return;
    }

    float s = 0.f;
#pragma unroll
    for (int l = 0; l < LL; l++) {
        val[l] = __expf(val[l] - mx);
        s += val[l];
    }
    float inv = 1.f / s;
#pragma unroll
    for (int l = 0; l < LL; l++) {
        float q = val[l] * inv;
        g_q[l * NN + n] = q;
        g_qb[l * NN + n] = __float2bfloat16(q);
    }
    float4 z4 = make_float4(0.f, 0.f, 0.f, 0.f);
    float4* P4 = (float4*)(g_P + (size_t)n * 32);
#pragma unroll
    for (int k = 0; k < 8; k++) P4[k] = z4;
}

// ---------------- host launch ----------------
extern "C" void kernel_launch(void* const* d_in, const int* in_sizes, int n_in,
                              void* d_out, int out_size) {
    (void)in_sizes; (void)n_in; (void)out_size;
    const float* image  = (const float*)d_in[0];
    const float* logits = (const float*)d_in[1];
    const float* wsp    = (const float*)d_in[2];
    const float* wbi    = (const float*)d_in[3];
    const float* comp   = (const float*)d_in[4];
    float* out = (float*)d_out;

    setup_k<<<1, 441>>>(wsp, wbi, comp);
    featq_k<<<16, 256>>>(image);
    buildK_k<<<dim3(32, 128), 128>>>();
    softmax0_k<<<64, 64>>>(logits);

    for (int it = 0; it < 5; it++) {
        sg_k<<<149, 256>>>();
        cs_k<<<64, 64>>>(logits, out, it == 4 ? 1 : 0);
    }
}

// round 12
// speedup vs baseline: 2.1955x; 1.2273x over previous
#include <cuda_runtime.h>
#include <cuda_bf16.h>
#include <math.h>
#include <stdint.h>

#define NN 4096          // D*W*H = 16*16*16
#define LL 21            // labels
#define LN (LL * NN)

// ---------------- device scratch ----------------
__device__ __nv_bfloat16 g_Kb[16777216];   // 4096x4096 bilateral kernel bf16 (32 MB, L2-resident)
__device__ float         g_F[NN * 8];      // features f0..f5, h, pad
__device__ float         g_q[LN];          // softmax out (fp32, spatial path)
__device__ __nv_bfloat16 g_qb[24 * NN];    // bf16 q rows 0..20, row21=ones, 22..23=0
__device__ float         g_A[LN];          // spatial filter result
__device__ float         g_P[NN * 32];     // bilateral GEMM out, col 21 = normalizer
__device__ float         g_Msp[LL * LL];
__device__ float         g_Mbi[LL * LL];
__device__ float         g_G[16];
__device__ float         g_S[16];

// ---------------- HMMA helper (plain sm_103 PTX legal) ----------------
__device__ __forceinline__ void mma16816(float* c, const uint32_t* a, const uint32_t* b) {
    asm volatile(
        "mma.sync.aligned.m16n8k16.row.col.f32.bf16.bf16.f32 "
        "{%0,%1,%2,%3}, {%4,%5,%6,%7}, {%8,%9}, {%0,%1,%2,%3};"
        : "+f"(c[0]), "+f"(c[1]), "+f"(c[2]), "+f"(c[3])
        : "r"(a[0]), "r"(a[1]), "r"(a[2]), "r"(a[3]), "r"(b[0]), "r"(b[1]));
}

// ---------------- setup ----------------
__global__ void setup_k(const float* __restrict__ wsp,
                        const float* __restrict__ wbi,
                        const float* __restrict__ comp) {
    int t = threadIdx.x;
    if (t < 16) {
        g_G[t] = expf(-0.5f * (float)(t * t));
        float s = 0.f;
        for (int u = 0; u < 16; u++) {
            int d = t - u;
            s += expf(-0.5f * (float)(d * d));
        }
        g_S[t] = s;
    }
    if (t < LL * LL) {
        int l = t / LL, m = t % LL;
        float s1 = 0.f, s2 = 0.f;
        for (int k = 0; k < LL; k++) {
            float c = comp[l * LL + k];
            s1 += c * wsp[k * LL + m];
            s2 += c * wbi[k * LL + m];
        }
        g_Msp[t] = s1;
        g_Mbi[t] = s2;
    }
}

// ---------------- features + initial softmax + qb + zero P (one launch) ----------------
__global__ void __launch_bounds__(128) featsm_k(const float* __restrict__ img,
                                                const float* __restrict__ logits) {
    int n = blockIdx.x * 128 + threadIdx.x;
    // features
    {
        float z = (float)(n >> 8);
        float y = (float)((n >> 4) & 15);
        float x = (float)(n & 15);
        const float ia = 1.f / 67.f, ib = 1.f / 3.f;
        float f0 = z * ia, f1 = y * ia, f2 = x * ia;
        float f3 = img[n] * ib;
        float f4 = img[NN + n] * ib;
        float f5 = img[2 * NN + n] * ib;
        float h = -0.5f * (f0 * f0 + f1 * f1 + f2 * f2 + f3 * f3 + f4 * f4 + f5 * f5);
        float* p = g_F + (size_t)n * 8;
        p[0] = f0; p[1] = f1; p[2] = f2; p[3] = f3; p[4] = f4; p[5] = f5; p[6] = h; p[7] = 0.f;
        g_qb[21 * NN + n] = __float2bfloat16(1.0f);
        g_qb[22 * NN + n] = __float2bfloat16(0.0f);
        g_qb[23 * NN + n] = __float2bfloat16(0.0f);
    }
    // initial softmax over labels
    float v[LL];
    float m = -1e30f;
#pragma unroll
    for (int l = 0; l < LL; l++) {
        v[l] = logits[l * NN + n];
        m = fmaxf(m, v[l]);
    }
    float s = 0.f;
#pragma unroll
    for (int l = 0; l < LL; l++) {
        v[l] = __expf(v[l] - m);
        s += v[l];
    }
    float inv = 1.f / s;
#pragma unroll
    for (int l = 0; l < LL; l++) {
        float q = v[l] * inv;
        g_q[l * NN + n] = q;
        g_qb[l * NN + n] = __float2bfloat16(q);
    }
    float4 z4 = make_float4(0.f, 0.f, 0.f, 0.f);
    float4* P4 = (float4*)(g_P + (size_t)n * 32);
#pragma unroll
    for (int k = 0; k < 8; k++) P4[k] = z4;
}

// ---------------- K build: grid (16 jt, 128 ib), 128 thr ----------------
// lane covers 8 consecutive j (one 16B store), warp does 8 i-rows x 256 j.
__global__ void __launch_bounds__(128) buildK_k() {
    int w = threadIdx.x >> 5;
    int lane = threadIdx.x & 31;
    int jb = blockIdx.x * 256 + lane * 8;
    int ibase = blockIdx.y * 32 + w * 8;

    float fj[8][7];
#pragma unroll
    for (int s = 0; s < 8; s++) {
        const float4* fp = (const float4*)(g_F + (size_t)(jb + s) * 8);
        float4 a = fp[0];
        float4 b = fp[1];
        fj[s][0] = a.x; fj[s][1] = a.y; fj[s][2] = a.z; fj[s][3] = a.w;
        fj[s][4] = b.x; fj[s][5] = b.y; fj[s][6] = b.z;
    }

#pragma unroll 2
    for (int ii = 0; ii < 8; ii++) {
        int i = ibase + ii;
        const float4* fp = (const float4*)(g_F + (size_t)i * 8);
        float4 a = fp[0];
        float4 b = fp[1];  // b.z = h_i
        float o[8];
#pragma unroll
        for (int s = 0; s < 8; s++) {
            float e = b.z + fj[s][6]
                    + a.x * fj[s][0] + a.y * fj[s][1] + a.z * fj[s][2]
                    + b.x * fj[s][4] + b.y * fj[s][5] + a.w * fj[s][3];
            o[s] = __expf(fminf(e, 0.f));
        }
        __nv_bfloat162 p0 = __floats2bfloat162_rn(o[0], o[1]);
        __nv_bfloat162 p1 = __floats2bfloat162_rn(o[2], o[3]);
        __nv_bfloat162 p2 = __floats2bfloat162_rn(o[4], o[5]);
        __nv_bfloat162 p3 = __floats2bfloat162_rn(o[6], o[7]);
        uint4 v;
        v.x = *(uint32_t*)&p0;
        v.y = *(uint32_t*)&p1;
        v.z = *(uint32_t*)&p2;
        v.w = *(uint32_t*)&p3;
        *(uint4*)(g_Kb + (size_t)i * NN + jb) = v;
    }
}

// ---------------- fused spatial + bilateral gemm. grid 277 x 256 thr ----------------
// blocks 0..255: gemm (8 warps each -> 2048 warp-units: 128 row-tiles x 16 k-splits)
// blocks 256..276: separable spatial filter, label = bid-256
__global__ void __launch_bounds__(256) sg_k() {
    __shared__ float s0[4096];
    __shared__ float s1[4096];
    __shared__ float Gs[16];
    const int tid = threadIdx.x;
    const int bid = blockIdx.x;

    if (bid >= 256) {
        int l = bid - 256;
        if (tid < 16) Gs[tid] = g_G[tid];
        const float* src = g_q + (size_t)l * NN;
#pragma unroll
        for (int k = 0; k < 16; k++) s0[tid + k * 256] = src[tid + k * 256];
        __syncthreads();
#pragma unroll
        for (int k = 0; k < 16; k++) {
            int n = tid + k * 256;
            int x = n & 15, b = n - x;
            float a = 0.f;
#pragma unroll
            for (int tt = 0; tt < 16; tt++) {
                int d = x - tt; d = d < 0 ? -d : d;
                a += Gs[d] * s0[b + tt];
            }
            s1[n] = a;
        }
        __syncthreads();
#pragma unroll
        for (int k = 0; k < 16; k++) {
            int n = tid + k * 256;
            int y = (n >> 4) & 15, b = n - (y << 4);
            float a = 0.f;
#pragma unroll
            for (int tt = 0; tt < 16; tt++) {
                int d = y - tt; d = d < 0 ? -d : d;
                a += Gs[d] * s1[b + (tt << 4)];
            }
            s0[n] = a;
        }
        __syncthreads();
        float* dst = g_A + (size_t)l * NN;
#pragma unroll
        for (int k = 0; k < 16; k++) {
            int n = tid + k * 256;
            int z = n >> 8, b = n & 255;
            float a = 0.f;
#pragma unroll
            for (int tt = 0; tt < 16; tt++) {
                int d = z - tt; d = d < 0 ? -d : d;
                a += Gs[d] * s0[b + (tt << 8)];
            }
            dst[n] = a;
        }
        return;
    }

    // ---- gemm path: unit = (row-tile jt of 32 rows, ksplit of 256) ----
    int wid = tid >> 5, lane = tid & 31;
    int u = bid * 8 + wid;            // 0..2047
    int jt = u >> 4, ks = u & 15;
    int rb = jt * 32;
    int k0 = ks * 256;
    int g = lane >> 2, t = lane & 3;

    const __nv_bfloat16* pa[4];
    pa[0] = g_Kb + (size_t)(rb + g) * NN;
    pa[1] = g_Kb + (size_t)(rb + g + 8) * NN;
    pa[2] = g_Kb + (size_t)(rb + 16 + g) * NN;
    pa[3] = g_Kb + (size_t)(rb + 16 + g + 8) * NN;
    const __nv_bfloat16* pb[3];
    pb[0] = g_qb + (size_t)(g)*NN;
    pb[1] = g_qb + (size_t)(8 + g) * NN;
    pb[2] = g_qb + (size_t)(16 + g) * NN;

    float acc[2][3][4];
#pragma unroll
    for (int m = 0; m < 2; m++)
#pragma unroll
        for (int n = 0; n < 3; n++)
#pragma unroll
            for (int r = 0; r < 4; r++) acc[m][n][r] = 0.f;

#pragma unroll 4
    for (int kss = 0; kss < 16; kss++) {
        int kk = k0 + kss * 16 + t * 2;
        uint32_t a0[4], a1[4], b[3][2];
        a0[0] = *(const uint32_t*)(pa[0] + kk);
        a0[1] = *(const uint32_t*)(pa[1] + kk);
        a0[2] = *(const uint32_t*)(pa[0] + kk + 8);
        a0[3] = *(const uint32_t*)(pa[1] + kk + 8);
        a1[0] = *(const uint32_t*)(pa[2] + kk);
        a1[1] = *(const uint32_t*)(pa[3] + kk);
        a1[2] = *(const uint32_t*)(pa[2] + kk + 8);
        a1[3] = *(const uint32_t*)(pa[3] + kk + 8);
#pragma unroll
        for (int n = 0; n < 3; n++) {
            b[n][0] = *(const uint32_t*)(pb[n] + kk);
            b[n][1] = *(const uint32_t*)(pb[n] + kk + 8);
        }
#pragma unroll
        for (int n = 0; n < 3; n++) {
            mma16816(acc[0][n], a0, b[n]);
            mma16816(acc[1][n], a1, b[n]);
        }
    }

#pragma unroll
    for (int m = 0; m < 2; m++) {
        int r0 = rb + m * 16 + g;
#pragma unroll
        for (int n = 0; n < 3; n++) {
            int c = n * 8 + t * 2;
            if (c < 21) {
                atomicAdd(g_P + (size_t)r0 * 32 + c, acc[m][n][0]);
                atomicAdd(g_P + (size_t)r0 * 32 + c + 1, acc[m][n][1]);
                atomicAdd(g_P + (size_t)(r0 + 8) * 32 + c, acc[m][n][2]);
                atomicAdd(g_P + (size_t)(r0 + 8) * 32 + c + 1, acc[m][n][3]);
            }
        }
    }
}

// ---------------- fused combine + softmax (+ qb + zero P); last iter writes out ----------------
__global__ void __launch_bounds__(128) cs_k(const float* __restrict__ logits,
                                            float* __restrict__ out, int last) {
    __shared__ float Ms[LL * LL];
    __shared__ float Mb[LL * LL];
    int tid = threadIdx.x;
    for (int i = tid; i < LL * LL; i += 128) {
        Ms[i] = g_Msp[i];
        Mb[i] = g_Mbi[i];
    }
    __syncthreads();

    int n = blockIdx.x * 128 + tid;
    int z = n >> 8, y = (n >> 4) & 15, x = n & 15;
    float invs = 1.f / (g_S[z] * g_S[y] * g_S[x]);

    float p[22];
    {
        const float4* P4 = (const float4*)(g_P + (size_t)n * 32);
#pragma unroll
        for (int k = 0; k < 5; k++) {
            float4 v = P4[k];
            p[k * 4] = v.x; p[k * 4 + 1] = v.y; p[k * 4 + 2] = v.z; p[k * 4 + 3] = v.w;
        }
        float4 v = P4[5];
        p[20] = v.x; p[21] = v.y;
    }
    float invb = 1.f / p[21];

    float a[LL];
#pragma unroll
    for (int m = 0; m < LL; m++) a[m] = g_A[m * NN + n];

    float val[LL];
    float mx = -1e30f;
#pragma unroll
    for (int l = 0; l < LL; l++) {
        const float* ms = Ms + l * LL;
        const float* mb = Mb + l * LL;
        float ssp = 0.f, sbi = 0.f;
#pragma unroll
        for (int m = 0; m < LL; m++) {
            ssp += ms[m] * a[m];
            sbi += mb[m] * p[m];
        }
        float v = logits[l * NN + n] + ssp * invs + sbi * invb;
        val[l] = v;
        mx = fmaxf(mx, v);
    }

    if (last) {
#pragma unroll
        for (int l = 0; l < LL; l++) out[l * NN + n] = val[l];
        return;
    }

    float s = 0.f;
#pragma unroll
    for (int l = 0; l < LL; l++) {
        val[l] = __expf(val[l] - mx);
        s += val[l];
    }
    float inv = 1.f / s;
#pragma unroll
    for (int l = 0; l < LL; l++) {
        float q = val[l] * inv;
        g_q[l * NN + n] = q;
        g_qb[l * NN + n] = __float2bfloat16(q);
    }
    float4 z4 = make_float4(0.f, 0.f, 0.f, 0.f);
    float4* P4 = (float4*)(g_P + (size_t)n * 32);
#pragma unroll
    for (int k = 0; k < 8; k++) P4[k] = z4;
}

// ---------------- host launch ----------------
extern "C" void kernel_launch(void* const* d_in, const int* in_sizes, int n_in,
                              void* d_out, int out_size) {
    (void)in_sizes; (void)n_in; (void)out_size;
    const float* image  = (const float*)d_in[0];
    const float* logits = (const float*)d_in[1];
    const float* wsp    = (const float*)d_in[2];
    const float* wbi    = (const float*)d_in[3];
    const float* comp   = (const float*)d_in[4];
    float* out = (float*)d_out;

    setup_k<<<1, 441>>>(wsp, wbi, comp);
    featsm_k<<<32, 128>>>(image, logits);
    buildK_k<<<dim3(16, 128), 128>>>();

    for (int it = 0; it < 5; it++) {
        sg_k<<<277, 256>>>();
        cs_k<<<32, 128>>>(logits, out, it == 4 ? 1 : 0);
    }
}

// round 14
// speedup vs baseline: 2.6451x; 1.2048x over previous
#include <cuda_runtime.h>
#include <cuda_bf16.h>
#include <math.h>
#include <stdint.h>

#define NN 4096          // D*W*H = 16*16*16
#define LL 21            // labels
#define LN (LL * NN)

// ---------------- device scratch ----------------
__device__ __nv_bfloat16 g_Kb[16777216];   // 4096x4096 bilateral kernel bf16 (32 MB)
__device__ float         g_F[NN * 8];      // features f0..f5, h, pad
__device__ float         g_q[LN];          // softmax out (fp32, spatial path)
__device__ __nv_bfloat16 g_qb[24 * NN];    // bf16 q rows 0..20, row21=ones, 22..23=0
__device__ float         g_A[LN];          // spatial filter result
__device__ float         g_P[NN * 32];     // bilateral GEMM out, col 21 = normalizer
__device__ float         g_Msp[LL * LL];
__device__ float         g_Mbi[LL * LL];
__device__ float         g_G[16];
__device__ float         g_S[16];

// ---------------- HMMA helper (plain sm_103 PTX legal) ----------------
__device__ __forceinline__ void mma16816(float* c, uint32_t a0, uint32_t a1,
                                         uint32_t a2, uint32_t a3,
                                         uint32_t b0, uint32_t b1) {
    asm volatile(
        "mma.sync.aligned.m16n8k16.row.col.f32.bf16.bf16.f32 "
        "{%0,%1,%2,%3}, {%4,%5,%6,%7}, {%8,%9}, {%0,%1,%2,%3};"
        : "+f"(c[0]), "+f"(c[1]), "+f"(c[2]), "+f"(c[3])
        : "r"(a0), "r"(a1), "r"(a2), "r"(a3), "r"(b0), "r"(b1));
}

// ---------------- features + initial softmax + qb + zero P + setup (one launch) ----------------
__global__ void __launch_bounds__(128) featsm_k(const float* __restrict__ img,
                                                const float* __restrict__ logits,
                                                const float* __restrict__ wsp,
                                                const float* __restrict__ wbi,
                                                const float* __restrict__ comp) {
    if (blockIdx.x == 32) {
        // setup tables + small matrices
        int t0 = threadIdx.x;
        if (t0 < 16) {
            g_G[t0] = expf(-0.5f * (float)(t0 * t0));
            float s = 0.f;
            for (int u = 0; u < 16; u++) {
                int d = t0 - u;
                s += expf(-0.5f * (float)(d * d));
            }
            g_S[t0] = s;
        }
        for (int t = t0; t < LL * LL; t += 128) {
            int l = t / LL, m = t % LL;
            float s1 = 0.f, s2 = 0.f;
            for (int k = 0; k < LL; k++) {
                float c = comp[l * LL + k];
                s1 += c * wsp[k * LL + m];
                s2 += c * wbi[k * LL + m];
            }
            g_Msp[t] = s1;
            g_Mbi[t] = s2;
        }
        return;
    }
    int n = blockIdx.x * 128 + threadIdx.x;
    {
        float z = (float)(n >> 8);
        float y = (float)((n >> 4) & 15);
        float x = (float)(n & 15);
        const float ia = 1.f / 67.f, ib = 1.f / 3.f;
        float f0 = z * ia, f1 = y * ia, f2 = x * ia;
        float f3 = img[n] * ib;
        float f4 = img[NN + n] * ib;
        float f5 = img[2 * NN + n] * ib;
        float h = -0.5f * (f0 * f0 + f1 * f1 + f2 * f2 + f3 * f3 + f4 * f4 + f5 * f5);
        float* p = g_F + (size_t)n * 8;
        p[0] = f0; p[1] = f1; p[2] = f2; p[3] = f3; p[4] = f4; p[5] = f5; p[6] = h; p[7] = 0.f;
        g_qb[21 * NN + n] = __float2bfloat16(1.0f);
        g_qb[22 * NN + n] = __float2bfloat16(0.0f);
        g_qb[23 * NN + n] = __float2bfloat16(0.0f);
    }
    float v[LL];
    float m = -1e30f;
#pragma unroll
    for (int l = 0; l < LL; l++) {
        v[l] = logits[l * NN + n];
        m = fmaxf(m, v[l]);
    }
    float s = 0.f;
#pragma unroll
    for (int l = 0; l < LL; l++) {
        v[l] = __expf(v[l] - m);
        s += v[l];
    }
    float inv = 1.f / s;
#pragma unroll
    for (int l = 0; l < LL; l++) {
        float q = v[l] * inv;
        g_q[l * NN + n] = q;
        g_qb[l * NN + n] = __float2bfloat16(q);
    }
    float4 z4 = make_float4(0.f, 0.f, 0.f, 0.f);
    float4* P4 = (float4*)(g_P + (size_t)n * 32);
#pragma unroll
    for (int k = 0; k < 8; k++) P4[k] = z4;
}

// ---------------- K build: grid (16 jt, 128 ib), 128 thr ----------------
__global__ void __launch_bounds__(128) buildK_k() {
    int w = threadIdx.x >> 5;
    int lane = threadIdx.x & 31;
    int jb = blockIdx.x * 256 + lane * 8;
    int ibase = blockIdx.y * 32 + w * 8;

    float fj[8][7];
#pragma unroll
    for (int s = 0; s < 8; s++) {
        const float4* fp = (const float4*)(g_F + (size_t)(jb + s) * 8);
        float4 a = fp[0];
        float4 b = fp[1];
        fj[s][0] = a.x; fj[s][1] = a.y; fj[s][2] = a.z; fj[s][3] = a.w;
        fj[s][4] = b.x; fj[s][5] = b.y; fj[s][6] = b.z;
    }

#pragma unroll 2
    for (int ii = 0; ii < 8; ii++) {
        int i = ibase + ii;
        const float4* fp = (const float4*)(g_F + (size_t)i * 8);
        float4 a = fp[0];
        float4 b = fp[1];  // b.z = h_i
        float o[8];
#pragma unroll
        for (int s = 0; s < 8; s++) {
            float e = b.z + fj[s][6]
                    + a.x * fj[s][0] + a.y * fj[s][1] + a.z * fj[s][2]
                    + b.x * fj[s][4] + b.y * fj[s][5] + a.w * fj[s][3];
            o[s] = __expf(fminf(e, 0.f));
        }
        __nv_bfloat162 p0 = __floats2bfloat162_rn(o[0], o[1]);
        __nv_bfloat162 p1 = __floats2bfloat162_rn(o[2], o[3]);
        __nv_bfloat162 p2 = __floats2bfloat162_rn(o[4], o[5]);
        __nv_bfloat162 p3 = __floats2bfloat162_rn(o[6], o[7]);
        uint4 v;
        v.x = *(uint32_t*)&p0;
        v.y = *(uint32_t*)&p1;
        v.z = *(uint32_t*)&p2;
        v.w = *(uint32_t*)&p3;
        *(uint4*)(g_Kb + (size_t)i * NN + jb) = v;
    }
}

// ---------------- fused spatial + bilateral gemm. grid 533 x 256 thr ----------------
// blocks 0..511: gemm (8 warps -> 4096 warp-units: 128 row-tiles x 32 k-splits of 128)
// blocks 512..532: separable spatial filter, label = bid-512
// Fragment loads use a k-permutation (consistent for A and B): lane t owns cols
// t*8..t*8+7 of each 32-col pair-step -> one uint4 per row serves TWO ksteps.
__global__ void __launch_bounds__(256) sg_k() {
    __shared__ float s0[4096];
    __shared__ float s1[4096];
    __shared__ float Gs[16];
    const int tid = threadIdx.x;
    const int bid = blockIdx.x;

    if (bid >= 512) {
        int l = bid - 512;
        if (tid < 16) Gs[tid] = g_G[tid];
        const float* src = g_q + (size_t)l * NN;
#pragma unroll
        for (int k = 0; k < 16; k++) s0[tid + k * 256] = src[tid + k * 256];
        __syncthreads();
#pragma unroll
        for (int k = 0; k < 16; k++) {
            int n = tid + k * 256;
            int x = n & 15, b = n - x;
            float a = 0.f;
#pragma unroll
            for (int tt = 0; tt < 16; tt++) {
                int d = x - tt; d = d < 0 ? -d : d;
                a += Gs[d] * s0[b + tt];
            }
            s1[n] = a;
        }
        __syncthreads();
#pragma unroll
        for (int k = 0; k < 16; k++) {
            int n = tid + k * 256;
            int y = (n >> 4) & 15, b = n - (y << 4);
            float a = 0.f;
#pragma unroll
            for (int tt = 0; tt < 16; tt++) {
                int d = y - tt; d = d < 0 ? -d : d;
                a += Gs[d] * s1[b + (tt << 4)];
            }
            s0[n] = a;
        }
        __syncthreads();
        float* dst = g_A + (size_t)l * NN;
#pragma unroll
        for (int k = 0; k < 16; k++) {
            int n = tid + k * 256;
            int z = n >> 8, b = n & 255;
            float a = 0.f;
#pragma unroll
            for (int tt = 0; tt < 16; tt++) {
                int d = z - tt; d = d < 0 ? -d : d;
                a += Gs[d] * s0[b + (tt << 8)];
            }
            dst[n] = a;
        }
        return;
    }

    // ---- gemm path: unit = (row-tile jt of 32 rows, ksplit of 128) ----
    int wid = tid >> 5, lane = tid & 31;
    int u = bid * 8 + wid;            // 0..4095
    int jt = u >> 5, ks = u & 31;
    int rb = jt * 32;
    int k0 = ks * 128;
    int g = lane >> 2, t = lane & 3;

    const __nv_bfloat16* pa0 = g_Kb + (size_t)(rb + g) * NN;
    const __nv_bfloat16* pa1 = g_Kb + (size_t)(rb + g + 8) * NN;
    const __nv_bfloat16* pa2 = g_Kb + (size_t)(rb + 16 + g) * NN;
    const __nv_bfloat16* pa3 = g_Kb + (size_t)(rb + 16 + g + 8) * NN;
    const __nv_bfloat16* pb0 = g_qb + (size_t)(g)*NN;
    const __nv_bfloat16* pb1 = g_qb + (size_t)(8 + g) * NN;
    const __nv_bfloat16* pb2 = g_qb + (size_t)(16 + g) * NN;

    float acc[2][3][4];
#pragma unroll
    for (int m = 0; m < 2; m++)
#pragma unroll
        for (int n = 0; n < 3; n++)
#pragma unroll
            for (int r = 0; r < 4; r++) acc[m][n][r] = 0.f;

#pragma unroll
    for (int kp = 0; kp < 4; kp++) {   // 4 pair-steps x 32 cols = 128
        int kc = k0 + kp * 32 + t * 8;
        uint4 A0 = *(const uint4*)(pa0 + kc);
        uint4 A1 = *(const uint4*)(pa1 + kc);
        uint4 A2 = *(const uint4*)(pa2 + kc);
        uint4 A3 = *(const uint4*)(pa3 + kc);
        uint4 B0 = *(const uint4*)(pb0 + kc);
        uint4 B1 = *(const uint4*)(pb1 + kc);
        uint4 B2 = *(const uint4*)(pb2 + kc);
        // kstep 0: regs .x (chunk0) / .y (chunk1)
        mma16816(acc[0][0], A0.x, A1.x, A0.y, A1.y, B0.x, B0.y);
        mma16816(acc[0][1], A0.x, A1.x, A0.y, A1.y, B1.x, B1.y);
        mma16816(acc[0][2], A0.x, A1.x, A0.y, A1.y, B2.x, B2.y);
        mma16816(acc[1][0], A2.x, A3.x, A2.y, A3.y, B0.x, B0.y);
        mma16816(acc[1][1], A2.x, A3.x, A2.y, A3.y, B1.x, B1.y);
        mma16816(acc[1][2], A2.x, A3.x, A2.y, A3.y, B2.x, B2.y);
        // kstep 1: regs .z / .w
        mma16816(acc[0][0], A0.z, A1.z, A0.w, A1.w, B0.z, B0.w);
        mma16816(acc[0][1], A0.z, A1.z, A0.w, A1.w, B1.z, B1.w);
        mma16816(acc[0][2], A0.z, A1.z, A0.w, A1.w, B2.z, B2.w);
        mma16816(acc[1][0], A2.z, A3.z, A2.w, A3.w, B0.z, B0.w);
        mma16816(acc[1][1], A2.z, A3.z, A2.w, A3.w, B1.z, B1.w);
        mma16816(acc[1][2], A2.z, A3.z, A2.w, A3.w, B2.z, B2.w);
    }

#pragma unroll
    for (int m = 0; m < 2; m++) {
        int r0 = rb + m * 16 + g;
#pragma unroll
        for (int n = 0; n < 3; n++) {
            int c = n * 8 + t * 2;
            if (c < 21) {
                atomicAdd(g_P + (size_t)r0 * 32 + c, acc[m][n][0]);
                atomicAdd(g_P + (size_t)r0 * 32 + c + 1, acc[m][n][1]);
                atomicAdd(g_P + (size_t)(r0 + 8) * 32 + c, acc[m][n][2]);
                atomicAdd(g_P + (size_t)(r0 + 8) * 32 + c + 1, acc[m][n][3]);
            }
        }
    }
}

// ---------------- fused combine + softmax (+ qb + zero P); last iter writes out ----------------
__global__ void __launch_bounds__(128) cs_k(const float* __restrict__ logits,
                                            float* __restrict__ out, int last) {
    __shared__ float Ms[LL * LL];
    __shared__ float Mb[LL * LL];
    int tid = threadIdx.x;
    for (int i = tid; i < LL * LL; i += 128) {
        Ms[i] = g_Msp[i];
        Mb[i] = g_Mbi[i];
    }
    __syncthreads();

    int n = blockIdx.x * 128 + tid;
    int z = n >> 8, y = (n >> 4) & 15, x = n & 15;
    float invs = 1.f / (g_S[z] * g_S[y] * g_S[x]);

    float p[22];
    {
        const float4* P4 = (const float4*)(g_P + (size_t)n * 32);
#pragma unroll
        for (int k = 0; k < 5; k++) {
            float4 v = P4[k];
            p[k * 4] = v.x; p[k * 4 + 1] = v.y; p[k * 4 + 2] = v.z; p[k * 4 + 3] = v.w;
        }
        float4 v = P4[5];
        p[20] = v.x; p[21] = v.y;
    }
    float invb = 1.f / p[21];

    float a[LL];
#pragma unroll
    for (int m = 0; m < LL; m++) a[m] = g_A[m * NN + n];

    float val[LL];
    float mx = -1e30f;
#pragma unroll
    for (int l = 0; l < LL; l++) {
        const float* ms = Ms + l * LL;
        const float* mb = Mb + l * LL;
        float ssp = 0.f, sbi = 0.f;
#pragma unroll
        for (int m = 0; m < LL; m++) {
            ssp += ms[m] * a[m];
            sbi += mb[m] * p[m];
        }
        float v = logits[l * NN + n] + ssp * invs + sbi * invb;
        val[l] = v;
        mx = fmaxf(mx, v);
    }

    if (last) {
#pragma unroll
        for (int l = 0; l < LL; l++) out[l * NN + n] = val[l];
        return;
    }

    float s = 0.f;
#pragma unroll
    for (int l = 0; l < LL; l++) {
        val[l] = __expf(val[l] - mx);
        s += val[l];
    }
    float inv = 1.f / s;
#pragma unroll
    for (int l = 0; l < LL; l++) {
        float q = val[l] * inv;
        g_q[l * NN + n] = q;
        g_qb[l * NN + n] = __float2bfloat16(q);
    }
    float4 z4 = make_float4(0.f, 0.f, 0.f, 0.f);
    float4* P4 = (float4*)(g_P + (size_t)n * 32);
#pragma unroll
    for (int k = 0; k < 8; k++) P4[k] = z4;
}

// ---------------- host launch ----------------
extern "C" void kernel_launch(void* const* d_in, const int* in_sizes, int n_in,
                              void* d_out, int out_size) {
    (void)in_sizes; (void)n_in; (void)out_size;
    const float* image  = (const float*)d_in[0];
    const float* logits = (const float*)d_in[1];
    const float* wsp    = (const float*)d_in[2];
    const float* wbi    = (const float*)d_in[3];
    const float* comp   = (const float*)d_in[4];
    float* out = (float*)d_out;

    featsm_k<<<33, 128>>>(image, logits, wsp, wbi, comp);
    buildK_k<<<dim3(16, 128), 128>>>();

    for (int it = 0; it < 5; it++) {
        sg_k<<<533, 256>>>();
        cs_k<<<32, 128>>>(logits, out, it == 4 ? 1 : 0);
    }
}

// round 15
// speedup vs baseline: 3.1854x; 1.2043x over previous
#include <cuda_runtime.h>
#include <cuda_bf16.h>
#include <math.h>
#include <stdint.h>

#define NN 4096          // D*W*H = 16*16*16
#define LL 21            // labels
#define LN (LL * NN)

// ---------------- device scratch ----------------
__device__ __nv_bfloat16 g_Kb[16777216];   // 4096x4096 bilateral kernel bf16 (32 MB)
__device__ float         g_F[NN * 8];      // features f0..f5, h, pad
__device__ float         g_q[LN];          // softmax out (fp32, spatial path)
__device__ __nv_bfloat16 g_qb[24 * NN];    // bf16 q rows 0..20, row21=ones, 22..23=0
__device__ float         g_A[LN];          // spatial filter result
__device__ float         g_P[32 * NN];     // bilateral GEMM out, COLUMN-major: P[c][n]; c=21 = normalizer
__device__ float         g_Msp[LL * LL];
__device__ float         g_Mbi[LL * LL];
__device__ float         g_G[16];
__device__ float         g_S[16];

// ---------------- HMMA helper (plain sm_103 PTX legal) ----------------
__device__ __forceinline__ void mma16816(float* c, uint32_t a0, uint32_t a1,
                                         uint32_t a2, uint32_t a3,
                                         uint32_t b0, uint32_t b1) {
    asm volatile(
        "mma.sync.aligned.m16n8k16.row.col.f32.bf16.bf16.f32 "
        "{%0,%1,%2,%3}, {%4,%5,%6,%7}, {%8,%9}, {%0,%1,%2,%3};"
        : "+f"(c[0]), "+f"(c[1]), "+f"(c[2]), "+f"(c[3])
        : "r"(a0), "r"(a1), "r"(a2), "r"(a3), "r"(b0), "r"(b1));
}

// ---------------- features + initial softmax + qb + zero P + setup (one launch) ----------------
__global__ void __launch_bounds__(128) featsm_k(const float* __restrict__ img,
                                                const float* __restrict__ logits,
                                                const float* __restrict__ wsp,
                                                const float* __restrict__ wbi,
                                                const float* __restrict__ comp) {
    if (blockIdx.x == 32) {
        int t0 = threadIdx.x;
        if (t0 < 16) {
            g_G[t0] = expf(-0.5f * (float)(t0 * t0));
            float s = 0.f;
            for (int u = 0; u < 16; u++) {
                int d = t0 - u;
                s += expf(-0.5f * (float)(d * d));
            }
            g_S[t0] = s;
        }
        for (int t = t0; t < LL * LL; t += 128) {
            int l = t / LL, m = t % LL;
            float s1 = 0.f, s2 = 0.f;
            for (int k = 0; k < LL; k++) {
                float c = comp[l * LL + k];
                s1 += c * wsp[k * LL + m];
                s2 += c * wbi[k * LL + m];
            }
            g_Msp[t] = s1;
            g_Mbi[t] = s2;
        }
        return;
    }
    int n = blockIdx.x * 128 + threadIdx.x;
    {
        float z = (float)(n >> 8);
        float y = (float)((n >> 4) & 15);
        float x = (float)(n & 15);
        const float ia = 1.f / 67.f, ib = 1.f / 3.f;
        float f0 = z * ia, f1 = y * ia, f2 = x * ia;
        float f3 = img[n] * ib;
        float f4 = img[NN + n] * ib;
        float f5 = img[2 * NN + n] * ib;
        float h = -0.5f * (f0 * f0 + f1 * f1 + f2 * f2 + f3 * f3 + f4 * f4 + f5 * f5);
        float* p = g_F + (size_t)n * 8;
        p[0] = f0; p[1] = f1; p[2] = f2; p[3] = f3; p[4] = f4; p[5] = f5; p[6] = h; p[7] = 0.f;
        g_qb[21 * NN + n] = __float2bfloat16(1.0f);
        g_qb[22 * NN + n] = __float2bfloat16(0.0f);
        g_qb[23 * NN + n] = __float2bfloat16(0.0f);
    }
    float v[LL];
    float m = -1e30f;
#pragma unroll
    for (int l = 0; l < LL; l++) {
        v[l] = logits[l * NN + n];
        m = fmaxf(m, v[l]);
    }
    float s = 0.f;
#pragma unroll
    for (int l = 0; l < LL; l++) {
        v[l] = __expf(v[l] - m);
        s += v[l];
    }
    float inv = 1.f / s;
#pragma unroll
    for (int l = 0; l < LL; l++) {
        float q = v[l] * inv;
        g_q[l * NN + n] = q;
        g_qb[l * NN + n] = __float2bfloat16(q);
    }
#pragma unroll
    for (int m2 = 0; m2 < 32; m2++) g_P[m2 * NN + n] = 0.f;  // coalesced per warp
}

// ---------------- K build: grid (16 jt, 128 ib), 128 thr ----------------
__global__ void __launch_bounds__(128) buildK_k() {
    int w = threadIdx.x >> 5;
    int lane = threadIdx.x & 31;
    int jb = blockIdx.x * 256 + lane * 8;
    int ibase = blockIdx.y * 32 + w * 8;

    float fj[8][7];
#pragma unroll
    for (int s = 0; s < 8; s++) {
        const float4* fp = (const float4*)(g_F + (size_t)(jb + s) * 8);
        float4 a = fp[0];
        float4 b = fp[1];
        fj[s][0] = a.x; fj[s][1] = a.y; fj[s][2] = a.z; fj[s][3] = a.w;
        fj[s][4] = b.x; fj[s][5] = b.y; fj[s][6] = b.z;
    }

#pragma unroll 2
    for (int ii = 0; ii < 8; ii++) {
        int i = ibase + ii;
        const float4* fp = (const float4*)(g_F + (size_t)i * 8);
        float4 a = fp[0];
        float4 b = fp[1];  // b.z = h_i
        float o[8];
#pragma unroll
        for (int s = 0; s < 8; s++) {
            float e = b.z + fj[s][6]
                    + a.x * fj[s][0] + a.y * fj[s][1] + a.z * fj[s][2]
                    + b.x * fj[s][4] + b.y * fj[s][5] + a.w * fj[s][3];
            o[s] = __expf(fminf(e, 0.f));
        }
        __nv_bfloat162 p0 = __floats2bfloat162_rn(o[0], o[1]);
        __nv_bfloat162 p1 = __floats2bfloat162_rn(o[2], o[3]);
        __nv_bfloat162 p2 = __floats2bfloat162_rn(o[4], o[5]);
        __nv_bfloat162 p3 = __floats2bfloat162_rn(o[6], o[7]);
        uint4 v;
        v.x = *(uint32_t*)&p0;
        v.y = *(uint32_t*)&p1;
        v.z = *(uint32_t*)&p2;
        v.w = *(uint32_t*)&p3;
        *(uint4*)(g_Kb + (size_t)i * NN + jb) = v;
    }
}

// ---------------- fused spatial + bilateral gemm. grid 533 x 256 thr ----------------
__global__ void __launch_bounds__(256) sg_k() {
    __shared__ float s0[4096];
    __shared__ float s1[4096];
    __shared__ float Gs[16];
    const int tid = threadIdx.x;
    const int bid = blockIdx.x;

    if (bid >= 512) {
        int l = bid - 512;
        if (tid < 16) Gs[tid] = g_G[tid];
        const float* src = g_q + (size_t)l * NN;
#pragma unroll
        for (int k = 0; k < 16; k++) s0[tid + k * 256] = src[tid + k * 256];
        __syncthreads();
#pragma unroll
        for (int k = 0; k < 16; k++) {
            int n = tid + k * 256;
            int x = n & 15, b = n - x;
            float a = 0.f;
#pragma unroll
            for (int tt = 0; tt < 16; tt++) {
                int d = x - tt; d = d < 0 ? -d : d;
                a += Gs[d] * s0[b + tt];
            }
            s1[n] = a;
        }
        __syncthreads();
#pragma unroll
        for (int k = 0; k < 16; k++) {
            int n = tid + k * 256;
            int y = (n >> 4) & 15, b = n - (y << 4);
            float a = 0.f;
#pragma unroll
            for (int tt = 0; tt < 16; tt++) {
                int d = y - tt; d = d < 0 ? -d : d;
                a += Gs[d] * s1[b + (tt << 4)];
            }
            s0[n] = a;
        }
        __syncthreads();
        float* dst = g_A + (size_t)l * NN;
#pragma unroll
        for (int k = 0; k < 16; k++) {
            int n = tid + k * 256;
            int z = n >> 8, b = n & 255;
            float a = 0.f;
#pragma unroll
            for (int tt = 0; tt < 16; tt++) {
                int d = z - tt; d = d < 0 ? -d : d;
                a += Gs[d] * s0[b + (tt << 8)];
            }
            dst[n] = a;
        }
        return;
    }

    // ---- gemm path: unit = (row-tile jt of 32 rows, ksplit of 128) ----
    int wid = tid >> 5, lane = tid & 31;
    int u = bid * 8 + wid;            // 0..4095
    int jt = u >> 5, ks = u & 31;
    int rb = jt * 32;
    int k0 = ks * 128;
    int g = lane >> 2, t = lane & 3;

    const __nv_bfloat16* pa0 = g_Kb + (size_t)(rb + g) * NN;
    const __nv_bfloat16* pa1 = g_Kb + (size_t)(rb + g + 8) * NN;
    const __nv_bfloat16* pa2 = g_Kb + (size_t)(rb + 16 + g) * NN;
    const __nv_bfloat16* pa3 = g_Kb + (size_t)(rb + 16 + g + 8) * NN;
    const __nv_bfloat16* pb0 = g_qb + (size_t)(g)*NN;
    const __nv_bfloat16* pb1 = g_qb + (size_t)(8 + g) * NN;
    const __nv_bfloat16* pb2 = g_qb + (size_t)(16 + g) * NN;

    float acc[2][3][4];
#pragma unroll
    for (int m = 0; m < 2; m++)
#pragma unroll
        for (int n = 0; n < 3; n++)
#pragma unroll
            for (int r = 0; r < 4; r++) acc[m][n][r] = 0.f;

#pragma unroll
    for (int kp = 0; kp < 4; kp++) {   // 4 pair-steps x 32 cols = 128
        int kc = k0 + kp * 32 + t * 8;
        uint4 A0 = *(const uint4*)(pa0 + kc);
        uint4 A1 = *(const uint4*)(pa1 + kc);
        uint4 A2 = *(const uint4*)(pa2 + kc);
        uint4 A3 = *(const uint4*)(pa3 + kc);
        uint4 B0 = *(const uint4*)(pb0 + kc);
        uint4 B1 = *(const uint4*)(pb1 + kc);
        uint4 B2 = *(const uint4*)(pb2 + kc);
        mma16816(acc[0][0], A0.x, A1.x, A0.y, A1.y, B0.x, B0.y);
        mma16816(acc[0][1], A0.x, A1.x, A0.y, A1.y, B1.x, B1.y);
        mma16816(acc[0][2], A0.x, A1.x, A0.y, A1.y, B2.x, B2.y);
        mma16816(acc[1][0], A2.x, A3.x, A2.y, A3.y, B0.x, B0.y);
        mma16816(acc[1][1], A2.x, A3.x, A2.y, A3.y, B1.x, B1.y);
        mma16816(acc[1][2], A2.x, A3.x, A2.y, A3.y, B2.x, B2.y);
        mma16816(acc[0][0], A0.z, A1.z, A0.w, A1.w, B0.z, B0.w);
        mma16816(acc[0][1], A0.z, A1.z, A0.w, A1.w, B1.z, B1.w);
        mma16816(acc[0][2], A0.z, A1.z, A0.w, A1.w, B2.z, B2.w);
        mma16816(acc[1][0], A2.z, A3.z, A2.w, A3.w, B0.z, B0.w);
        mma16816(acc[1][1], A2.z, A3.z, A2.w, A3.w, B1.z, B1.w);
        mma16816(acc[1][2], A2.z, A3.z, A2.w, A3.w, B2.z, B2.w);
    }

    // P is column-major now: atomicAdd(g_P + c*NN + row)
#pragma unroll
    for (int m = 0; m < 2; m++) {
        int r0 = rb + m * 16 + g;
#pragma unroll
        for (int n = 0; n < 3; n++) {
            int c = n * 8 + t * 2;
            if (c < 21) {
                atomicAdd(g_P + (size_t)c * NN + r0, acc[m][n][0]);
                atomicAdd(g_P + (size_t)(c + 1) * NN + r0, acc[m][n][1]);
                atomicAdd(g_P + (size_t)c * NN + r0 + 8, acc[m][n][2]);
                atomicAdd(g_P + (size_t)(c + 1) * NN + r0 + 8, acc[m][n][3]);
            }
        }
    }
}

// ---------------- fused combine + softmax v2: grid 128 x 256 thr ----------------
// block = 32 voxels x 8 label-chunks (3 labels each, chunks 0..6 active for matvec).
// All loads warp-coalesced (P now column-major). Softmax via 2 smem reductions.
__global__ void __launch_bounds__(256) cs_k(const float* __restrict__ logits,
                                            float* __restrict__ out, int last) {
    __shared__ float Ms[LL * LL];
    __shared__ float Mb[LL * LL];
    __shared__ float redM[8][32];
    __shared__ float redS[8][32];
    int tid = threadIdx.x;
    for (int i = tid; i < LL * LL; i += 256) {
        Ms[i] = g_Msp[i];
        Mb[i] = g_Mbi[i];
    }
    __syncthreads();

    int w = tid & 31;                 // voxel within block
    int chunk = tid >> 5;             // 0..7
    int n = blockIdx.x * 32 + w;
    int l0 = chunk * 3;               // chunk 7 -> l0=21 (no labels)

    int z = n >> 8, y = (n >> 4) & 15, x = n & 15;
    float invs = 1.f / (g_S[z] * g_S[y] * g_S[x]);

    // coalesced loads: all 22 P rows + 21 A rows at this voxel
    float p[22];
#pragma unroll
    for (int m = 0; m < 22; m++) p[m] = g_P[m * NN + n];
    float invb = 1.f / p[21];
    float a[LL];
#pragma unroll
    for (int m = 0; m < LL; m++) a[m] = g_A[m * NN + n];

    float val[3];
    float mx = -1e30f;
    if (l0 < LL) {
#pragma unroll
        for (int j = 0; j < 3; j++) {
            int l = l0 + j;
            const float* ms = Ms + l * LL;
            const float* mb = Mb + l * LL;
            float ssp = 0.f, sbi = 0.f;
#pragma unroll
            for (int m = 0; m < LL; m++) {
                ssp += ms[m] * a[m];
                sbi += mb[m] * p[m];
            }
            float v = logits[l * NN + n] + ssp * invs + sbi * invb;
            val[j] = v;
            mx = fmaxf(mx, v);
        }
    }

    if (last) {
        if (l0 < LL) {
#pragma unroll
            for (int j = 0; j < 3; j++) out[(l0 + j) * NN + n] = val[j];
        }
        return;
    }

    // cross-chunk max
    redM[chunk][w] = mx;
    __syncthreads();
    float gmx = redM[0][w];
#pragma unroll
    for (int c = 1; c < 7; c++) gmx = fmaxf(gmx, redM[c][w]);

    float psum = 0.f;
    if (l0 < LL) {
#pragma unroll
        for (int j = 0; j < 3; j++) {
            val[j] = __expf(val[j] - gmx);
            psum += val[j];
        }
    }
    redS[chunk][w] = psum;
    __syncthreads();
    float s = redS[0][w];
#pragma unroll
    for (int c = 1; c < 7; c++) s += redS[c][w];
    float inv = 1.f / s;

    if (l0 < LL) {
#pragma unroll
        for (int j = 0; j < 3; j++) {
            float q = val[j] * inv;
            g_q[(l0 + j) * NN + n] = q;
            g_qb[(l0 + j) * NN + n] = __float2bfloat16(q);
        }
    }
    // zero P rows for next iteration: chunk c zeroes rows 4c..4c+3 (coalesced)
#pragma unroll
    for (int r = 0; r < 4; r++) g_P[(chunk * 4 + r) * NN + n] = 0.f;
}

// ---------------- host launch ----------------
extern "C" void kernel_launch(void* const* d_in, const int* in_sizes, int n_in,
                              void* d_out, int out_size) {
    (void)in_sizes; (void)n_in; (void)out_size;
    const float* image  = (const float*)d_in[0];
    const float* logits = (const float*)d_in[1];
    const float* wsp    = (const float*)d_in[2];
    const float* wbi    = (const float*)d_in[3];
    const float* comp   = (const float*)d_in[4];
    float* out = (float*)d_out;

    featsm_k<<<33, 128>>>(image, logits, wsp, wbi, comp);
    buildK_k<<<dim3(16, 128), 128>>>();

    for (int it = 0; it < 5; it++) {
        sg_k<<<533, 256>>>();
        cs_k<<<128, 256>>>(logits, out, it == 4 ? 1 : 0);
    }
}